// round 15
// baseline (speedup 1.0000x reference)
#include <cuda_runtime.h>
#include <cuda_fp16.h>
#include <cstdint>

#define B_SZ   4096
#define IN_SZ  1024
#define HID_SZ 2048
#define OUT_SZ 512

// ---------------- scratch (device globals; no allocation) ----------------
__device__ __align__(128) __half g_Ak[(size_t)IN_SZ * B_SZ];    // psp fp16, NATIVE [IN][B]
__device__ __align__(128) __half g_Wh[(size_t)HID_SZ * IN_SZ];  // W_h    [HID][IN]
__device__ __align__(128) __half g_Wo[(size_t)OUT_SZ * HID_SZ]; // W_o    [OUT][HID]
__device__ __align__(128) __half g_R [(size_t)B_SZ * HID_SZ];   // rate   [B][HID]

// ---------------- helpers ----------------
__device__ __forceinline__ uint32_t su32(const void* p) {
    uint32_t a;
    asm("{ .reg .u64 t; cvta.to.shared.u64 t, %1; cvt.u32.u64 %0, t; }" : "=r"(a) : "l"(p));
    return a;
}
__device__ __forceinline__ void cp16(uint32_t s, const void* g) {
    asm volatile("cp.async.cg.shared.global [%0], [%1], 16;" :: "r"(s), "l"(g));
}
__device__ __forceinline__ void cp_arrive(uint32_t mbar) {
    asm volatile("cp.async.mbarrier.arrive.noinc.shared.b64 [%0];" :: "r"(mbar) : "memory");
}
__device__ __forceinline__ void mbar_init(uint32_t a, uint32_t cnt) {
    asm volatile("mbarrier.init.shared.b64 [%0], %1;" :: "r"(a), "r"(cnt) : "memory");
}
__device__ __forceinline__ void mbar_arrive(uint32_t a) {
    asm volatile("mbarrier.arrive.shared.b64 _, [%0];" :: "r"(a) : "memory");
}
__device__ __forceinline__ void mbar_wait(uint32_t mbar, uint32_t parity) {
    asm volatile(
        "{\n\t.reg .pred P;\n"
        "LAB_W%=:\n\t"
        "mbarrier.try_wait.parity.acquire.cta.shared::cta.b64 P, [%0], %1, 0x989680;\n\t"
        "@!P bra LAB_W%=;\n\t"
        "}"
        :: "r"(mbar), "r"(parity) : "memory");
}

#define LDSM4(r, addr) \
    asm volatile("ldmatrix.sync.aligned.m8n8.x4.shared.b16 {%0,%1,%2,%3}, [%4];" \
        : "=r"((r)[0]), "=r"((r)[1]), "=r"((r)[2]), "=r"((r)[3]) : "r"(addr))

#define LDSM4T(r, addr) \
    asm volatile("ldmatrix.sync.aligned.m8n8.x4.trans.shared.b16 {%0,%1,%2,%3}, [%4];" \
        : "=r"((r)[0]), "=r"((r)[1]), "=r"((r)[2]), "=r"((r)[3]) : "r"(addr))

#define MMA(d, a, b0, b1) \
    asm volatile("mma.sync.aligned.m16n8k16.row.col.f32.f16.f16.f32 " \
        "{%0,%1,%2,%3},{%4,%5,%6,%7},{%8,%9},{%0,%1,%2,%3};" \
        : "+f"((d)[0]), "+f"((d)[1]), "+f"((d)[2]), "+f"((d)[3]) \
        : "r"((a)[0]), "r"((a)[1]), "r"((a)[2]), "r"((a)[3]), "r"(b0), "r"(b1))

// ================= GEMM1: 128x128 tile, k-chunk 64, 3-stage mbar ring, trans-A ======
// A smem stage: [64 k-rows][256B] (128 m fp16/row), swizzle ch ^= (krow & 7)
// B smem stage: [128 n-rows][128B], swizzle ch ^= (nrow & 7)  (unchanged champion)
// A fragments via ldmatrix.x4.trans: per-kt address = aBase[mt] + kt*4096 (XOR is
// kt-invariant because krow&7 == lane&7 for all kt).
// rate = 0.35*sigmoid((6/7)*(acc + b_h)) -> g_R fp16
__global__ __launch_bounds__(256, 2)
void k_gemm1(const float* __restrict__ bias)
{
    constexpr int KDIM = IN_SZ;
    constexpr uint32_t BOFF  = 16384u;                 // A region: 64*256B
    constexpr uint32_t STAGE = BOFF + 16384u;          // + B: 128*128B
    constexpr uint32_t MBAR  = 3u * STAGE;

    extern __shared__ __align__(1024) uint8_t smem[];
    const uint32_t sbase = su32(smem);
    const uint32_t mbF = sbase + MBAR;
    const uint32_t mbE = sbase + MBAR + 24;

    const int tid = threadIdx.x, lane = tid & 31, wid = tid >> 5;
    const int m0 = blockIdx.x * 128, n0 = blockIdx.y * 128;
    const int wm0 = (wid >> 2) * 64, wn0 = (wid & 3) * 32;

    if (tid == 0) {
#pragma unroll
        for (int s = 0; s < 3; s++) {
            mbar_init(mbF + 8u * s, 256);
            mbar_init(mbE + 8u * s, 8);
        }
    }
    __syncthreads();

    // ---- cp.async mapping ----
    // A: 64 k-rows x 16 chunks; thread -> row tid>>2, chunks (tid&3)*4 + j
    const int lrA = tid >> 2, chA0 = (tid & 3) * 4;
    const __half* pA = g_Ak + (size_t)lrA * B_SZ + m0 + chA0 * 8;
    uint32_t uAoff[4];
#pragma unroll
    for (int j = 0; j < 4; j++)
        uAoff[j] = (uint32_t)(lrA * 256 + (((chA0 + j) ^ (lrA & 7)) << 4));
    // B: 128 n-rows x 8 chunks; thread -> row tid>>3 (+32j), chunk tid&7
    const int lrB = tid >> 3, chB = tid & 7;
    const uint32_t uBoff = (uint32_t)(lrB * 128 + ((chB ^ (lrB & 7)) << 4));
    const __half* pB = g_Wh + (size_t)(n0 + lrB) * KDIM + chB * 8;

    // ---- ldmatrix bases ----
    // A (.trans): lane -> krow = (lane&7) + 8*(lane>>4); mchunk = wm0/8 + 2*mt + ((lane>>3)&1)
    const int krl = (lane & 7) + 8 * (lane >> 4);
    uint32_t aBase[4];
#pragma unroll
    for (int mt = 0; mt < 4; mt++) {
        const int mch = wm0 / 8 + 2 * mt + ((lane >> 3) & 1);
        aBase[mt] = sbase + (uint32_t)(krl * 256 + ((mch ^ (lane & 7)) << 4));
    }
    // B (non-trans, champion)
    const int bch = (lane >> 3) & 1;
    uint32_t bBase[2], bSw[2];
#pragma unroll
    for (int nt = 0; nt < 2; nt++) {
        const int r = wn0 + (lane & 7) + ((lane >> 4) << 3) + nt * 16;
        bBase[nt] = sbase + BOFF + (uint32_t)(r * 128);
        bSw[nt] = (uint32_t)(r & 7);
    }

    float c[4][4][4];
#pragma unroll
    for (int i = 0; i < 4; i++)
#pragma unroll
        for (int j = 0; j < 4; j++)
#pragma unroll
            for (int r = 0; r < 4; r++) c[i][j][r] = 0.0f;

    auto produce = [&](int kc) {
        const int s = kc % 3;
        const uint32_t so = (uint32_t)s * STAGE;
        const __half* gA = pA + (size_t)kc * 64 * B_SZ;
        const __half* gB = pB + (size_t)kc * 64;
#pragma unroll
        for (int j = 0; j < 4; j++)
            cp16(sbase + so + uAoff[j], gA + j * 8);
#pragma unroll
        for (int j = 0; j < 4; j++)
            cp16(sbase + BOFF + so + uBoff + j * 4096u, gB + (size_t)j * 32 * KDIM);
        cp_arrive(mbF + 8u * s);
    };

    constexpr int NC = KDIM / 64;
    produce(0);
    produce(1);
    produce(2);
#pragma unroll 1
    for (int kc = 0; kc < NC; kc++) {
        const int s = kc % 3;
        mbar_wait(mbF + 8u * s, (uint32_t)((kc / 3) & 1));
        const uint32_t so = (uint32_t)s * STAGE;
#pragma unroll
        for (int kt = 0; kt < 4; kt++) {
            uint32_t af[4][4], bf[2][4];
#pragma unroll
            for (int mt = 0; mt < 4; mt++)
                LDSM4T(af[mt], aBase[mt] + so + (uint32_t)(kt * 4096));
#pragma unroll
            for (int nt = 0; nt < 2; nt++) {
                const uint32_t ch = (uint32_t)(kt * 2 + bch) ^ bSw[nt];
                LDSM4(bf[nt], bBase[nt] + so + (ch << 4));
            }
#pragma unroll
            for (int mt = 0; mt < 4; mt++)
#pragma unroll
                for (int n8 = 0; n8 < 4; n8++)
                    MMA(c[mt][n8], af[mt], bf[n8 >> 1][(n8 & 1) * 2],
                                            bf[n8 >> 1][(n8 & 1) * 2 + 1]);
        }
        __syncwarp();
        if (lane == 0) mbar_arrive(mbE + 8u * s);
        const int kn = kc + 3;
        if (kn < NC) {
            mbar_wait(mbE + 8u * s, (uint32_t)((kc / 3) & 1));
            produce(kn);
        }
    }

    // ---- epilogue ----
    const int mrow = m0 + wm0 + (lane >> 2);
    const int ncol = n0 + wn0 + 2 * (lane & 3);
    const float S = 6.0f / 7.0f;
#pragma unroll
    for (int n8 = 0; n8 < 4; n8++) {
        const int n = ncol + n8 * 8;
        const float b0 = bias[n], b1 = bias[n + 1];
#pragma unroll
        for (int mt = 0; mt < 4; mt++) {
            const int m = mrow + mt * 16;
#pragma unroll
            for (int h = 0; h < 2; h++) {
                const float v0 = S * (c[mt][n8][2 * h]     + b0);
                const float v1 = S * (c[mt][n8][2 * h + 1] + b1);
                const __half2 r = __floats2half2_rn(0.35f / (1.0f + __expf(-v0)),
                                                    0.35f / (1.0f + __expf(-v1)));
                *reinterpret_cast<__half2*>(g_R + (size_t)(m + 8 * h) * HID_SZ + n) = r;
            }
        }
    }
}

// ================= GEMM2: 64x128 tile, k-chunk 64, 4-stage ring, produce-first ======
// out = 0.35*sigmoid(0.75*acc + 0.75*b_o + 0.125*label) -> fp32
__global__ __launch_bounds__(256, 2)
void k_gemm2(const float* __restrict__ bias, const float* __restrict__ label,
             float* __restrict__ out)
{
    constexpr int KDIM = HID_SZ;
    constexpr uint32_t BOFF  = 64u * 128u;             // A: 64 m-rows x 128B
    constexpr uint32_t STAGE = BOFF + 16384u;          // + B: 128 rows x 128B = 24576
    constexpr uint32_t MBAR  = 4u * STAGE;

    extern __shared__ __align__(1024) uint8_t smem[];
    const uint32_t sbase = su32(smem);
    const uint32_t mbF = sbase + MBAR;
    const uint32_t mbE = sbase + MBAR + 32;

    const int tid = threadIdx.x, lane = tid & 31, wid = tid >> 5;
    const int m0 = blockIdx.x * 64, n0 = blockIdx.y * 128;
    const int wm0 = (wid >> 2) * 32, wn0 = (wid & 3) * 32;

    if (tid == 0) {
#pragma unroll
        for (int s = 0; s < 4; s++) {
            mbar_init(mbF + 8u * s, 256);
            mbar_init(mbE + 8u * s, 8);
        }
    }
    __syncthreads();

    // ---- cp.async mapping (champion: [row][128B], ch ^= row&7) ----
    const int lrow = tid >> 3, lch = tid & 7;
    const uint32_t sOff = (uint32_t)(lrow * 128 + ((lch ^ (lrow & 7)) << 4));
    const __half* pA = g_R  + (size_t)(m0 + lrow) * KDIM + lch * 8;
    const __half* pB = g_Wo + (size_t)(n0 + lrow) * KDIM + lch * 8;

    // ---- ldmatrix bases ----
    const int ach = lane >> 4;
    const int bch = (lane >> 3) & 1;
    uint32_t aBase[2], aSw[2], bBase[2], bSw[2];
#pragma unroll
    for (int mt = 0; mt < 2; mt++) {
        const int r = wm0 + (lane & 15) + mt * 16;
        aBase[mt] = sbase + (uint32_t)(r * 128);
        aSw[mt] = (uint32_t)(r & 7);
    }
#pragma unroll
    for (int nt = 0; nt < 2; nt++) {
        const int r = wn0 + (lane & 7) + ((lane >> 4) << 3) + nt * 16;
        bBase[nt] = sbase + BOFF + (uint32_t)(r * 128);
        bSw[nt] = (uint32_t)(r & 7);
    }

    float c[2][4][4];
#pragma unroll
    for (int i = 0; i < 2; i++)
#pragma unroll
        for (int j = 0; j < 4; j++)
#pragma unroll
            for (int r = 0; r < 4; r++) c[i][j][r] = 0.0f;

    auto produce = [&](int kc) {
        const int s = kc & 3;
        const size_t ko = (size_t)kc * 64;
        const uint32_t so = (uint32_t)s * STAGE;
#pragma unroll
        for (int j = 0; j < 2; j++)           // A: 64 rows, 32/pass
            cp16(sbase + so + sOff + j * 4096u, pA + ko + (size_t)j * 32 * KDIM);
#pragma unroll
        for (int j = 0; j < 4; j++)           // B: 128 rows
            cp16(sbase + BOFF + so + sOff + j * 4096u, pB + ko + (size_t)j * 32 * KDIM);
        cp_arrive(mbF + 8u * s);
    };

    constexpr int NC = KDIM / 64;             // 32
    produce(0);
    produce(1);
    produce(2);
#pragma unroll 1
    for (int kc = 0; kc < NC; kc++) {
        const int s = kc & 3;
        const int kn = kc + 3;
        if (kn < NC) {                        // produce BEFORE consuming (slot (kc+3)&3)
            if (kn >= 4)
                mbar_wait(mbE + 8u * (kn & 3), (uint32_t)(((kn / 4) - 1) & 1));
            produce(kn);
        }
        mbar_wait(mbF + 8u * s, (uint32_t)((kc / 4) & 1));
        const uint32_t so = (uint32_t)s * STAGE;
#pragma unroll
        for (int kt = 0; kt < 4; kt++) {
            uint32_t af[2][4], bf[2][4];
#pragma unroll
            for (int mt = 0; mt < 2; mt++) {
                const uint32_t ch = (uint32_t)(kt * 2 + ach) ^ aSw[mt];
                LDSM4(af[mt], aBase[mt] + so + (ch << 4));
            }
#pragma unroll
            for (int nt = 0; nt < 2; nt++) {
                const uint32_t ch = (uint32_t)(kt * 2 + bch) ^ bSw[nt];
                LDSM4(bf[nt], bBase[nt] + so + (ch << 4));
            }
#pragma unroll
            for (int mt = 0; mt < 2; mt++)
#pragma unroll
                for (int n8 = 0; n8 < 4; n8++)
                    MMA(c[mt][n8], af[mt], bf[n8 >> 1][(n8 & 1) * 2],
                                            bf[n8 >> 1][(n8 & 1) * 2 + 1]);
        }
        __syncwarp();
        if (lane == 0) mbar_arrive(mbE + 8u * s);
    }

    // ---- epilogue ----
    const int mrow = m0 + wm0 + (lane >> 2);
    const int ncol = n0 + wn0 + 2 * (lane & 3);
#pragma unroll
    for (int n8 = 0; n8 < 4; n8++) {
        const int n = ncol + n8 * 8;
        const float b0 = 0.75f * bias[n], b1 = 0.75f * bias[n + 1];
#pragma unroll
        for (int mt = 0; mt < 2; mt++) {
            const int m = mrow + mt * 16;
#pragma unroll
            for (int h = 0; h < 2; h++) {
                const int mm = m + 8 * h;
                const float2 lb = *reinterpret_cast<const float2*>(
                    label + (size_t)mm * OUT_SZ + n);
                const float v0 = 0.75f * c[mt][n8][2 * h]     + b0 + 0.125f * lb.x;
                const float v1 = 0.75f * c[mt][n8][2 * h + 1] + b1 + 0.125f * lb.y;
                float2 o;
                o.x = 0.35f / (1.0f + __expf(-v0));
                o.y = 0.35f / (1.0f + __expf(-v1));
                *reinterpret_cast<float2*>(out + (size_t)mm * OUT_SZ + n) = o;
            }
        }
    }
}

// ================= prep (single launch): pure streaming converts, no smem ===========
// psp fp32 [IN][B] -> g_Ak fp16 same layout; W_h, W_o fp32 -> fp16.
__global__ void k_prep(const float4* __restrict__ psp4,
                       const float4* __restrict__ Wh, const float4* __restrict__ Wo) {
    constexpr int NPSP_BLK = IN_SZ * B_SZ / 8 / 1024;    // 512 (uint4 outputs / 1024)
    constexpr int N4H = HID_SZ * IN_SZ / 4;              // 524288
    constexpr int N4O = OUT_SZ * HID_SZ / 4;             // 262144
    const int bid = blockIdx.x, tid = threadIdx.x;

    if (bid < NPSP_BLK) {
        const int base = bid * 1024 + tid;               // uint4 output index
#pragma unroll
        for (int j = 0; j < 4; j++) {
            const int o = base + j * 256;
            const float4 f0 = psp4[2 * o];
            const float4 f1 = psp4[2 * o + 1];
            __half2 h[4];
            h[0] = __floats2half2_rn(f0.x, f0.y);
            h[1] = __floats2half2_rn(f0.z, f0.w);
            h[2] = __floats2half2_rn(f1.x, f1.y);
            h[3] = __floats2half2_rn(f1.z, f1.w);
            *reinterpret_cast<uint4*>(g_Ak + (size_t)o * 8) = *reinterpret_cast<uint4*>(h);
        }
        return;
    }
    const int base = (bid - NPSP_BLK) * 1024 + tid;
#pragma unroll
    for (int j = 0; j < 4; j++) {
        const int i = base + j * 256;
        const float4* src;
        __half* dst;
        int idx;
        if (i < N4H)            { src = Wh; dst = g_Wh; idx = i; }
        else if (i < N4H + N4O) { src = Wo; dst = g_Wo; idx = i - N4H; }
        else continue;
        const float4 v = src[idx];
        const __half2 h0 = __floats2half2_rn(v.x, v.y);
        const __half2 h1 = __floats2half2_rn(v.z, v.w);
        uint2 u;
        u.x = *reinterpret_cast<const uint32_t*>(&h0);
        u.y = *reinterpret_cast<const uint32_t*>(&h1);
        *reinterpret_cast<uint2*>(dst + (size_t)idx * 4) = u;
    }
}

// ---------------- launcher ----------------
extern "C" void kernel_launch(void* const* d_in, const int* in_sizes, int n_in,
                              void* d_out, int out_size) {
    const float* psp   = (const float*)d_in[0];  // [1024, 4096]
    const float* label = (const float*)d_in[1];  // [4096, 512]
    const float* W_h   = (const float*)d_in[2];  // [2048, 1024]
    const float* b_h   = (const float*)d_in[3];  // [2048]
    const float* W_o   = (const float*)d_in[4];  // [512, 2048]
    const float* b_o   = (const float*)d_in[5];  // [512]
    float* out = (float*)d_out;                  // [4096, 512]

    const int SMEM1 = 3 * 32768 + 64;            // 3 stages + mbarriers
    const int SMEM2 = 4 * 24576 + 96;            // 4 stages + mbarriers
    cudaFuncSetAttribute(k_gemm1, cudaFuncAttributeMaxDynamicSharedMemorySize, SMEM1);
    cudaFuncSetAttribute(k_gemm2, cudaFuncAttributeMaxDynamicSharedMemorySize, SMEM2);

    const int PREP_BLOCKS = IN_SZ * B_SZ / 8 / 1024
                          + (HID_SZ * IN_SZ / 4 + OUT_SZ * HID_SZ / 4 + 1023) / 1024;
    k_prep<<<PREP_BLOCKS, 256>>>((const float4*)psp, (const float4*)W_h, (const float4*)W_o);

    k_gemm1<<<dim3(B_SZ / 128, HID_SZ / 128), 256, SMEM1>>>(b_h);
    k_gemm2<<<dim3(B_SZ / 64,  OUT_SZ / 128), 256, SMEM2>>>(b_o, label, out);
}

// round 16
// speedup vs baseline: 1.0061x; 1.0061x over previous
#include <cuda_runtime.h>
#include <cuda_fp16.h>
#include <cstdint>

#define B_SZ   4096
#define IN_SZ  1024
#define HID_SZ 2048
#define OUT_SZ 512

// ---------------- scratch (device globals; no allocation) ----------------
__device__ __align__(128) __half g_At[(size_t)B_SZ * IN_SZ];    // psp^T  [B][IN]  fp16
__device__ __align__(128) __half g_Wh[(size_t)HID_SZ * IN_SZ];  // W_h    [HID][IN]
__device__ __align__(128) __half g_Wo[(size_t)OUT_SZ * HID_SZ]; // W_o    [OUT][HID]
__device__ __align__(128) __half g_R [(size_t)B_SZ * HID_SZ];   // rate   [B][HID]

__device__ int g_next;       // fused work counter (reset by k_prep each call)
__device__ int g_cnt[32];    // per-128-row m-block GEMM1 completion counters

// ---------------- helpers ----------------
__device__ __forceinline__ uint32_t su32(const void* p) {
    uint32_t a;
    asm("{ .reg .u64 t; cvta.to.shared.u64 t, %1; cvt.u32.u64 %0, t; }" : "=r"(a) : "l"(p));
    return a;
}
__device__ __forceinline__ void cp16(uint32_t s, const void* g) {
    asm volatile("cp.async.cg.shared.global [%0], [%1], 16;" :: "r"(s), "l"(g));
}
__device__ __forceinline__ void cp_arrive(uint32_t mbar) {
    asm volatile("cp.async.mbarrier.arrive.noinc.shared.b64 [%0];" :: "r"(mbar) : "memory");
}
__device__ __forceinline__ void mbar_init(uint32_t a, uint32_t cnt) {
    asm volatile("mbarrier.init.shared.b64 [%0], %1;" :: "r"(a), "r"(cnt) : "memory");
}
__device__ __forceinline__ void mbar_arrive(uint32_t a) {
    asm volatile("mbarrier.arrive.shared.b64 _, [%0];" :: "r"(a) : "memory");
}
__device__ __forceinline__ void mbar_wait(uint32_t mbar, uint32_t parity) {
    asm volatile(
        "{\n\t.reg .pred P;\n"
        "LAB_W%=:\n\t"
        "mbarrier.try_wait.parity.acquire.cta.shared::cta.b64 P, [%0], %1, 0x989680;\n\t"
        "@!P bra LAB_W%=;\n\t"
        "}"
        :: "r"(mbar), "r"(parity) : "memory");
}

#define LDSM4(r, addr) \
    asm volatile("ldmatrix.sync.aligned.m8n8.x4.shared.b16 {%0,%1,%2,%3}, [%4];" \
        : "=r"((r)[0]), "=r"((r)[1]), "=r"((r)[2]), "=r"((r)[3]) : "r"(addr))

#define MMA(d, a, b0, b1) \
    asm volatile("mma.sync.aligned.m16n8k16.row.col.f32.f16.f16.f32 " \
        "{%0,%1,%2,%3},{%4,%5,%6,%7},{%8,%9},{%0,%1,%2,%3};" \
        : "+f"((d)[0]), "+f"((d)[1]), "+f"((d)[2]), "+f"((d)[3]) \
        : "r"((a)[0]), "r"((a)[1]), "r"((a)[2]), "r"((a)[3]), "r"(b0), "r"(b1))

// ---------------- GEMM tile body (R14 champion mainloop, parameterized origin) ------
// MTx128 tile at (m0, n0), k-chunk 64, 3-stage mbarrier ring.
// smem tiles: [rows][128B]; 16B-chunk swizzle: ch ^= (row & 7)
// full[s]: count 256 (cp.async group completion); free[s]: count 8 (1 arrive/warp)
// EPI=0: rate = 0.35*sigmoid((6/7)*(acc + b)) -> g_R fp16
// EPI=1: out  = 0.35*sigmoid(0.75*acc + 0.75*b + 0.125*label) -> out fp32
template<int KDIM, int EPI, int MT>
__device__ __forceinline__ void gemm_tile(
    uint32_t sbase, int m0, int n0,
    const float* __restrict__ bias, const float* __restrict__ label,
    float* __restrict__ out)
{
    constexpr int NMT = MT / 32;
    constexpr uint32_t BOFF  = (uint32_t)MT * 128u;
    constexpr uint32_t STAGE = BOFF + 16384u;
    constexpr uint32_t MBAR  = 3u * STAGE;

    const __half* __restrict__ Ag = (EPI == 0) ? g_At : g_R;
    const __half* __restrict__ Bg = (EPI == 0) ? g_Wh : g_Wo;

    const uint32_t mbF = sbase + MBAR;
    const uint32_t mbE = sbase + MBAR + 24;

    const int tid = threadIdx.x, lane = tid & 31, wid = tid >> 5;
    const int wm0 = (wid >> 2) * (MT / 2), wn0 = (wid & 3) * 32;

    // per-tile barrier (re)init; caller's __syncthreads ordered prior arrives
    if (tid == 0) {
#pragma unroll
        for (int s = 0; s < 3; s++) {
            mbar_init(mbF + 8u * s, 256);
            mbar_init(mbE + 8u * s, 8);
        }
    }
    __syncthreads();

    const int lrow = tid >> 3;
    const int lch  = tid & 7;
    const uint32_t sOff = (uint32_t)(lrow * 128 + ((lch ^ (lrow & 7)) << 4));
    const __half* pA = Ag + (size_t)(m0 + lrow) * KDIM + lch * 8;
    const __half* pB = Bg + (size_t)(n0 + lrow) * KDIM + lch * 8;
    const uint32_t uA = sbase + sOff;
    const uint32_t uB = sbase + BOFF + sOff;

    const int ach = lane >> 4;
    const int bch = (lane >> 3) & 1;
    uint32_t aBase[NMT], aSw[NMT], bBase[2], bSw[2];
#pragma unroll
    for (int mt = 0; mt < NMT; mt++) {
        const int r = wm0 + (lane & 15) + mt * 16;
        aBase[mt] = sbase + (uint32_t)(r * 128);
        aSw[mt] = (uint32_t)(r & 7);
    }
#pragma unroll
    for (int nt = 0; nt < 2; nt++) {
        const int r = wn0 + (lane & 7) + ((lane >> 4) << 3) + nt * 16;
        bBase[nt] = sbase + BOFF + (uint32_t)(r * 128);
        bSw[nt] = (uint32_t)(r & 7);
    }

    float c[NMT][4][4];
#pragma unroll
    for (int i = 0; i < NMT; i++)
#pragma unroll
        for (int j = 0; j < 4; j++)
#pragma unroll
            for (int r = 0; r < 4; r++) c[i][j][r] = 0.0f;

    auto produce = [&](int kc) {
        const int s = kc % 3;
        const size_t ko = (size_t)kc * 64;
        const uint32_t so = (uint32_t)s * STAGE;
#pragma unroll
        for (int j = 0; j < MT / 32; j++)
            cp16(uA + so + j * 4096u, pA + ko + (size_t)j * 32 * KDIM);
#pragma unroll
        for (int j = 0; j < 4; j++)
            cp16(uB + so + j * 4096u, pB + ko + (size_t)j * 32 * KDIM);
        cp_arrive(mbF + 8u * s);
    };

    constexpr int NC = KDIM / 64;
    produce(0);
    produce(1);
    produce(2);
#pragma unroll 1
    for (int kc = 0; kc < NC; kc++) {
        const int s = kc % 3;
        mbar_wait(mbF + 8u * s, (uint32_t)((kc / 3) & 1));
        const uint32_t so = (uint32_t)s * STAGE;
#pragma unroll
        for (int kt = 0; kt < 4; kt++) {
            uint32_t af[NMT][4], bf[2][4];
#pragma unroll
            for (int mt = 0; mt < NMT; mt++) {
                const uint32_t ch = (uint32_t)(kt * 2 + ach) ^ aSw[mt];
                LDSM4(af[mt], aBase[mt] + so + (ch << 4));
            }
#pragma unroll
            for (int nt = 0; nt < 2; nt++) {
                const uint32_t ch = (uint32_t)(kt * 2 + bch) ^ bSw[nt];
                LDSM4(bf[nt], bBase[nt] + so + (ch << 4));
            }
#pragma unroll
            for (int mt = 0; mt < NMT; mt++)
#pragma unroll
                for (int n8 = 0; n8 < 4; n8++)
                    MMA(c[mt][n8], af[mt], bf[n8 >> 1][(n8 & 1) * 2],
                                            bf[n8 >> 1][(n8 & 1) * 2 + 1]);
        }
        __syncwarp();
        if (lane == 0) mbar_arrive(mbE + 8u * s);
        const int kn = kc + 3;
        if (kn < NC) {
            mbar_wait(mbE + 8u * s, (uint32_t)((kc / 3) & 1));
            produce(kn);
        }
    }

    // ---- epilogue ----
    const int mrow = m0 + wm0 + (lane >> 2);
    const int ncol = n0 + wn0 + 2 * (lane & 3);
#pragma unroll
    for (int n8 = 0; n8 < 4; n8++) {
        const int n = ncol + n8 * 8;
        const float b0 = bias[n], b1 = bias[n + 1];
#pragma unroll
        for (int mt = 0; mt < NMT; mt++) {
            const int m = mrow + mt * 16;
            if (EPI == 0) {
                const float S = 6.0f / 7.0f;
#pragma unroll
                for (int h = 0; h < 2; h++) {
                    const float v0 = S * (c[mt][n8][2 * h]     + b0);
                    const float v1 = S * (c[mt][n8][2 * h + 1] + b1);
                    const __half2 r = __floats2half2_rn(0.35f / (1.0f + __expf(-v0)),
                                                        0.35f / (1.0f + __expf(-v1)));
                    *reinterpret_cast<__half2*>(g_R + (size_t)(m + 8 * h) * HID_SZ + n) = r;
                }
            } else {
#pragma unroll
                for (int h = 0; h < 2; h++) {
                    const int mm = m + 8 * h;
                    const float2 lb = *reinterpret_cast<const float2*>(
                        label + (size_t)mm * OUT_SZ + n);
                    const float v0 = 0.75f * c[mt][n8][2 * h]     + 0.75f * b0 + 0.125f * lb.x;
                    const float v1 = 0.75f * c[mt][n8][2 * h + 1] + 0.75f * b1 + 0.125f * lb.y;
                    float2 o;
                    o.x = 0.35f / (1.0f + __expf(-v0));
                    o.y = 0.35f / (1.0f + __expf(-v1));
                    *reinterpret_cast<float2*>(out + (size_t)mm * OUT_SZ + n) = o;
                }
            }
        }
    }
}

// ---------------- fused persistent GEMM1+GEMM2 ----------------
// Work ids: [0,512)   GEMM1 tiles, m-major: m = id>>4, n = id&15
//           [512,768) GEMM2 tiles: id2 = id-512, m2 = id2>>2, n2 = id2&3
// GEMM2 tile gates on g_cnt[m2>>1] == 16 (its g_R m-block fully produced).
__global__ __launch_bounds__(256, 2)
void k_fused(const float* __restrict__ b_h, const float* __restrict__ b_o,
             const float* __restrict__ label, float* __restrict__ out)
{
    extern __shared__ __align__(1024) uint8_t smem[];
    const uint32_t sbase = su32(smem);
    __shared__ int sh_id;
    const int tid = threadIdx.x;

#pragma unroll 1
    for (;;) {
        __syncthreads();                               // orders prior tile's arrives
        if (tid == 0) sh_id = atomicAdd(&g_next, 1);
        __syncthreads();
        const int id = sh_id;
        if (id >= 768) return;

        if (id < 512) {
            const int m0 = (id >> 4) * 128, n0 = (id & 15) * 128;
            gemm_tile<IN_SZ, 0, 128>(sbase, m0, n0, b_h, nullptr, nullptr);
            __threadfence();                           // publish g_R stores
            __syncthreads();
            if (tid == 0) atomicAdd(&g_cnt[id >> 4], 1);
        } else {
            const int id2 = id - 512;
            const int m2 = id2 >> 2, n2 = id2 & 3;
            if (tid == 0) {
                while (atomicAdd(&g_cnt[m2 >> 1], 0) < 16) __nanosleep(128);
            }
            __syncthreads();
            __threadfence();                           // acquire side
            gemm_tile<HID_SZ, 1, 64>(sbase, m2 * 64, n2 * 128, b_o, label, out);
        }
    }
}

// ---------------- prep (single launch): counter reset + transpose + converts --------
__global__ void k_prep(const float* __restrict__ psp,
                       const float4* __restrict__ Wh, const float4* __restrict__ Wo) {
    constexpr int NBB = B_SZ / 128;                      // 32 b-tiles
    constexpr int NT_BLK = NBB * (IN_SZ / 32);           // 1024 transpose blocks
    constexpr int N4H = HID_SZ * IN_SZ / 4;              // 524288
    constexpr int N4O = OUT_SZ * HID_SZ / 4;             // 262144
    const int bid = blockIdx.x, tid = threadIdx.x;

    if (bid == 0) {                                      // reset fused-kernel counters
        if (tid < 32) g_cnt[tid] = 0;
        else if (tid == 32) g_next = 0;
    }

    if (bid < NT_BLK) {
        __shared__ float t[32][133];
        const int b0 = (bid % NBB) * 128;
        const int k0 = (bid / NBB) * 32;
#pragma unroll
        for (int i = 0; i < 4; i++) {
            const int idx = tid + i * 256;
            const int r = idx >> 5, cc = idx & 31;
            const float4 v = *reinterpret_cast<const float4*>(
                psp + (size_t)(k0 + r) * B_SZ + b0 + cc * 4);
            t[r][cc * 4 + 0] = v.x; t[r][cc * 4 + 1] = v.y;
            t[r][cc * 4 + 2] = v.z; t[r][cc * 4 + 3] = v.w;
        }
        __syncthreads();
#pragma unroll
        for (int i = 0; i < 2; i++) {
            const int idx = tid + i * 256;
            const int b = idx >> 2, kc = idx & 3;
            __half2 h[4];
#pragma unroll
            for (int j = 0; j < 4; j++)
                h[j] = __floats2half2_rn(t[kc * 8 + 2 * j][b], t[kc * 8 + 2 * j + 1][b]);
            *reinterpret_cast<uint4*>(g_At + (size_t)(b0 + b) * IN_SZ + k0 + kc * 8) =
                *reinterpret_cast<uint4*>(h);
        }
        return;
    }
    // weight convert: 4 float4s per thread, independent (MLP=4)
    const int base = (bid - NT_BLK) * 1024 + tid;
#pragma unroll
    for (int j = 0; j < 4; j++) {
        const int i = base + j * 256;
        const float4* src;
        __half* dst;
        int idx;
        if (i < N4H)            { src = Wh; dst = g_Wh; idx = i; }
        else if (i < N4H + N4O) { src = Wo; dst = g_Wo; idx = i - N4H; }
        else continue;
        const float4 v = src[idx];
        const __half2 h0 = __floats2half2_rn(v.x, v.y);
        const __half2 h1 = __floats2half2_rn(v.z, v.w);
        uint2 u;
        u.x = *reinterpret_cast<const uint32_t*>(&h0);
        u.y = *reinterpret_cast<const uint32_t*>(&h1);
        *reinterpret_cast<uint2*>(dst + (size_t)idx * 4) = u;
    }
}

// ---------------- launcher ----------------
extern "C" void kernel_launch(void* const* d_in, const int* in_sizes, int n_in,
                              void* d_out, int out_size) {
    const float* psp   = (const float*)d_in[0];  // [1024, 4096]
    const float* label = (const float*)d_in[1];  // [4096, 512]
    const float* W_h   = (const float*)d_in[2];  // [2048, 1024]
    const float* b_h   = (const float*)d_in[3];  // [2048]
    const float* W_o   = (const float*)d_in[4];  // [512, 2048]
    const float* b_o   = (const float*)d_in[5];  // [512]
    float* out = (float*)d_out;                  // [4096, 512]

    const int SMEM = 3 * 32768 + 64;             // covers both tile shapes
    cudaFuncSetAttribute(k_fused, cudaFuncAttributeMaxDynamicSharedMemorySize, SMEM);

    const int PREP_BLOCKS = (B_SZ / 128) * (IN_SZ / 32)
                          + (HID_SZ * IN_SZ / 4 + OUT_SZ * HID_SZ / 4 + 1023) / 1024;
    k_prep<<<PREP_BLOCKS, 256>>>(psp, (const float4*)W_h, (const float4*)W_o);

    k_fused<<<296, 256, SMEM>>>(b_h, b_o, label, out);
}

// round 17
// speedup vs baseline: 1.1144x; 1.1077x over previous
#include <cuda_runtime.h>
#include <cuda_fp16.h>
#include <cstdint>

#define B_SZ   4096
#define IN_SZ  1024
#define HID_SZ 2048
#define OUT_SZ 512

// ---------------- scratch (device globals; no allocation) ----------------
__device__ __align__(128) __half g_At[(size_t)B_SZ * IN_SZ];    // psp^T  [B][IN]  fp16
__device__ __align__(128) __half g_Wh[(size_t)HID_SZ * IN_SZ];  // W_h    [HID][IN]
__device__ __align__(128) __half g_Wo[(size_t)OUT_SZ * HID_SZ]; // W_o    [OUT][HID]
__device__ __align__(128) __half g_R [(size_t)B_SZ * HID_SZ];   // rate   [B][HID]
__device__ __align__(128) float  g_P [(size_t)2 * B_SZ * OUT_SZ]; // GEMM2 split-K partials

// ---------------- helpers ----------------
__device__ __forceinline__ uint32_t su32(const void* p) {
    uint32_t a;
    asm("{ .reg .u64 t; cvta.to.shared.u64 t, %1; cvt.u32.u64 %0, t; }" : "=r"(a) : "l"(p));
    return a;
}
__device__ __forceinline__ void cp16(uint32_t s, const void* g) {
    asm volatile("cp.async.cg.shared.global [%0], [%1], 16;" :: "r"(s), "l"(g));
}
__device__ __forceinline__ void cp_arrive(uint32_t mbar) {
    asm volatile("cp.async.mbarrier.arrive.noinc.shared.b64 [%0];" :: "r"(mbar) : "memory");
}
__device__ __forceinline__ void mbar_init(uint32_t a, uint32_t cnt) {
    asm volatile("mbarrier.init.shared.b64 [%0], %1;" :: "r"(a), "r"(cnt) : "memory");
}
__device__ __forceinline__ void mbar_arrive(uint32_t a) {
    asm volatile("mbarrier.arrive.shared.b64 _, [%0];" :: "r"(a) : "memory");
}
__device__ __forceinline__ void mbar_wait(uint32_t mbar, uint32_t parity) {
    asm volatile(
        "{\n\t.reg .pred P;\n"
        "LAB_W%=:\n\t"
        "mbarrier.try_wait.parity.acquire.cta.shared::cta.b64 P, [%0], %1, 0x989680;\n\t"
        "@!P bra LAB_W%=;\n\t"
        "}"
        :: "r"(mbar), "r"(parity) : "memory");
}

#define LDSM4(r, addr) \
    asm volatile("ldmatrix.sync.aligned.m8n8.x4.shared.b16 {%0,%1,%2,%3}, [%4];" \
        : "=r"((r)[0]), "=r"((r)[1]), "=r"((r)[2]), "=r"((r)[3]) : "r"(addr))

#define MMA(d, a, b0, b1) \
    asm volatile("mma.sync.aligned.m16n8k16.row.col.f32.f16.f16.f32 " \
        "{%0,%1,%2,%3},{%4,%5,%6,%7},{%8,%9},{%0,%1,%2,%3};" \
        : "+f"((d)[0]), "+f"((d)[1]), "+f"((d)[2]), "+f"((d)[3]) \
        : "r"((a)[0]), "r"((a)[1]), "r"((a)[2]), "r"((a)[3]), "r"(b0), "r"(b1))

// ---------------- GEMM: 128x128 CTA tile, k-chunk 64, 3-stage mbarrier ring ---------
// (R14 champion mainloop; 16 chunks per CTA in all instances)
// smem tiles: [rows][128B]; 16B-chunk swizzle: ch ^= (row & 7)
// full[s]: count 256 (cp.async); free[s]: count 8 (1 arrive/warp)
// EPI=0: rate = 0.35*sigmoid((6/7)*(acc + b)) -> g_R fp16          (KDIM=1024, z=1)
// EPI=2: raw fp32 partials -> g_P[z]                               (KDIM=2048, z=2, half-K each)
template<int KDIM, int EPI>
__global__ __launch_bounds__(256, 2)
void k_gemm(const float* __restrict__ bias)
{
    constexpr int MT = 128, NMT = 4;
    constexpr uint32_t BOFF  = 16384u;
    constexpr uint32_t STAGE = 32768u;
    constexpr uint32_t MBAR  = 3u * STAGE;
    constexpr int NC = (EPI == 2) ? (KDIM / 128) : (KDIM / 64);   // 16 both

    const __half* __restrict__ Ag = (EPI == 0) ? g_At : g_R;
    const __half* __restrict__ Bg = (EPI == 0) ? g_Wh : g_Wo;

    extern __shared__ __align__(1024) uint8_t smem[];
    const uint32_t sbase = su32(smem);
    const uint32_t mbF = sbase + MBAR;
    const uint32_t mbE = sbase + MBAR + 24;

    const int tid = threadIdx.x, lane = tid & 31, wid = tid >> 5;
    const int m0 = blockIdx.x * MT, n0 = blockIdx.y * 128;
    const int koff = (EPI == 2) ? (int)blockIdx.z * NC : 0;       // chunk offset
    const int wm0 = (wid >> 2) * 64, wn0 = (wid & 3) * 32;

    if (tid == 0) {
#pragma unroll
        for (int s = 0; s < 3; s++) {
            mbar_init(mbF + 8u * s, 256);
            mbar_init(mbE + 8u * s, 8);
        }
    }
    __syncthreads();

    // ---- cp.async mapping ----
    const int lrow = tid >> 3;
    const int lch  = tid & 7;
    const uint32_t sOff = (uint32_t)(lrow * 128 + ((lch ^ (lrow & 7)) << 4));
    const __half* pA = Ag + (size_t)(m0 + lrow) * KDIM + lch * 8;
    const __half* pB = Bg + (size_t)(n0 + lrow) * KDIM + lch * 8;
    const uint32_t uA = sbase + sOff;
    const uint32_t uB = sbase + BOFF + sOff;

    // ---- ldmatrix per-thread bases ----
    const int ach = lane >> 4;
    const int bch = (lane >> 3) & 1;
    uint32_t aBase[NMT], aSw[NMT], bBase[2], bSw[2];
#pragma unroll
    for (int mt = 0; mt < NMT; mt++) {
        const int r = wm0 + (lane & 15) + mt * 16;
        aBase[mt] = sbase + (uint32_t)(r * 128);
        aSw[mt] = (uint32_t)(r & 7);
    }
#pragma unroll
    for (int nt = 0; nt < 2; nt++) {
        const int r = wn0 + (lane & 7) + ((lane >> 4) << 3) + nt * 16;
        bBase[nt] = sbase + BOFF + (uint32_t)(r * 128);
        bSw[nt] = (uint32_t)(r & 7);
    }

    float c[NMT][4][4];
#pragma unroll
    for (int i = 0; i < NMT; i++)
#pragma unroll
        for (int j = 0; j < 4; j++)
#pragma unroll
            for (int r = 0; r < 4; r++) c[i][j][r] = 0.0f;

    auto produce = [&](int kc) {
        const int s = kc % 3;
        const size_t ko = (size_t)(koff + kc) * 64;
        const uint32_t so = (uint32_t)s * STAGE;
#pragma unroll
        for (int j = 0; j < 4; j++)
            cp16(uA + so + j * 4096u, pA + ko + (size_t)j * 32 * KDIM);
#pragma unroll
        for (int j = 0; j < 4; j++)
            cp16(uB + so + j * 4096u, pB + ko + (size_t)j * 32 * KDIM);
        cp_arrive(mbF + 8u * s);
    };

    produce(0);
    produce(1);
    produce(2);
#pragma unroll 1
    for (int kc = 0; kc < NC; kc++) {
        const int s = kc % 3;
        mbar_wait(mbF + 8u * s, (uint32_t)((kc / 3) & 1));
        const uint32_t so = (uint32_t)s * STAGE;
#pragma unroll
        for (int kt = 0; kt < 4; kt++) {
            uint32_t af[NMT][4], bf[2][4];
#pragma unroll
            for (int mt = 0; mt < NMT; mt++) {
                const uint32_t ch = (uint32_t)(kt * 2 + ach) ^ aSw[mt];
                LDSM4(af[mt], aBase[mt] + so + (ch << 4));
            }
#pragma unroll
            for (int nt = 0; nt < 2; nt++) {
                const uint32_t ch = (uint32_t)(kt * 2 + bch) ^ bSw[nt];
                LDSM4(bf[nt], bBase[nt] + so + (ch << 4));
            }
#pragma unroll
            for (int mt = 0; mt < NMT; mt++)
#pragma unroll
                for (int n8 = 0; n8 < 4; n8++)
                    MMA(c[mt][n8], af[mt], bf[n8 >> 1][(n8 & 1) * 2],
                                            bf[n8 >> 1][(n8 & 1) * 2 + 1]);
        }
        __syncwarp();
        if (lane == 0) mbar_arrive(mbE + 8u * s);
        const int kn = kc + 3;
        if (kn < NC) {
            mbar_wait(mbE + 8u * s, (uint32_t)((kc / 3) & 1));
            produce(kn);
        }
    }

    // ---- epilogue ----
    const int mrow = m0 + wm0 + (lane >> 2);
    const int ncol = n0 + wn0 + 2 * (lane & 3);
    if (EPI == 2) {
        float* dst = g_P + (size_t)blockIdx.z * B_SZ * OUT_SZ;
#pragma unroll
        for (int n8 = 0; n8 < 4; n8++) {
            const int n = ncol + n8 * 8;
#pragma unroll
            for (int mt = 0; mt < NMT; mt++) {
                const int m = mrow + mt * 16;
#pragma unroll
                for (int h = 0; h < 2; h++) {
                    float2 v;
                    v.x = c[mt][n8][2 * h];
                    v.y = c[mt][n8][2 * h + 1];
                    *reinterpret_cast<float2*>(dst + (size_t)(m + 8 * h) * OUT_SZ + n) = v;
                }
            }
        }
    } else {
        const float S = 6.0f / 7.0f;
#pragma unroll
        for (int n8 = 0; n8 < 4; n8++) {
            const int n = ncol + n8 * 8;
            const float b0 = bias[n], b1 = bias[n + 1];
#pragma unroll
            for (int mt = 0; mt < NMT; mt++) {
                const int m = mrow + mt * 16;
#pragma unroll
                for (int h = 0; h < 2; h++) {
                    const float v0 = S * (c[mt][n8][2 * h]     + b0);
                    const float v1 = S * (c[mt][n8][2 * h + 1] + b1);
                    const __half2 r = __floats2half2_rn(0.35f / (1.0f + __expf(-v0)),
                                                        0.35f / (1.0f + __expf(-v1)));
                    *reinterpret_cast<__half2*>(g_R + (size_t)(m + 8 * h) * HID_SZ + n) = r;
                }
            }
        }
    }
}

// ---------------- reduce: out = 0.35*sigmoid(0.75*(p0+p1) + 0.75*b_o + 0.125*label) --
__global__ void k_red(const float* __restrict__ bias, const float* __restrict__ label,
                      float* __restrict__ out) {
    const int idx = blockIdx.x * 256 + threadIdx.x;          // float4 index, 524288 total
    const float4 p0 = *reinterpret_cast<const float4*>(g_P + (size_t)idx * 4);
    const float4 p1 = *reinterpret_cast<const float4*>(g_P + (size_t)B_SZ * OUT_SZ + (size_t)idx * 4);
    const float4 lb = reinterpret_cast<const float4*>(label)[idx];
    const float4 bo = reinterpret_cast<const float4*>(bias)[idx & (OUT_SZ / 4 - 1)];
    float4 o;
    o.x = 0.35f / (1.0f + __expf(-(0.75f * (p0.x + p1.x) + 0.75f * bo.x + 0.125f * lb.x)));
    o.y = 0.35f / (1.0f + __expf(-(0.75f * (p0.y + p1.y) + 0.75f * bo.y + 0.125f * lb.y)));
    o.z = 0.35f / (1.0f + __expf(-(0.75f * (p0.z + p1.z) + 0.75f * bo.z + 0.125f * lb.z)));
    o.w = 0.35f / (1.0f + __expf(-(0.75f * (p0.w + p1.w) + 0.75f * bo.w + 0.125f * lb.w)));
    reinterpret_cast<float4*>(out)[idx] = o;
}

// ---------------- prep (single launch): psp transpose + both weight converts --------
__global__ void k_prep(const float* __restrict__ psp,
                       const float4* __restrict__ Wh, const float4* __restrict__ Wo) {
    constexpr int NBB = B_SZ / 128;                      // 32 b-tiles
    constexpr int NT_BLK = NBB * (IN_SZ / 32);           // 1024 transpose blocks
    constexpr int N4H = HID_SZ * IN_SZ / 4;              // 524288
    constexpr int N4O = OUT_SZ * HID_SZ / 4;             // 262144
    const int bid = blockIdx.x, tid = threadIdx.x;

    if (bid < NT_BLK) {
        __shared__ float t[32][133];
        const int b0 = (bid % NBB) * 128;
        const int k0 = (bid / NBB) * 32;
#pragma unroll
        for (int i = 0; i < 4; i++) {
            const int idx = tid + i * 256;
            const int r = idx >> 5, cc = idx & 31;
            const float4 v = __ldcs(reinterpret_cast<const float4*>(
                psp + (size_t)(k0 + r) * B_SZ + b0 + cc * 4));
            t[r][cc * 4 + 0] = v.x; t[r][cc * 4 + 1] = v.y;
            t[r][cc * 4 + 2] = v.z; t[r][cc * 4 + 3] = v.w;
        }
        __syncthreads();
#pragma unroll
        for (int i = 0; i < 2; i++) {
            const int idx = tid + i * 256;
            const int b = idx >> 2, kc = idx & 3;
            __half2 h[4];
#pragma unroll
            for (int j = 0; j < 4; j++)
                h[j] = __floats2half2_rn(t[kc * 8 + 2 * j][b], t[kc * 8 + 2 * j + 1][b]);
            *reinterpret_cast<uint4*>(g_At + (size_t)(b0 + b) * IN_SZ + k0 + kc * 8) =
                *reinterpret_cast<uint4*>(h);
        }
        return;
    }
    // weight convert: 4 float4s per thread, independent (MLP=4)
    const int base = (bid - NT_BLK) * 1024 + tid;
#pragma unroll
    for (int j = 0; j < 4; j++) {
        const int i = base + j * 256;
        const float4* src;
        __half* dst;
        int idx;
        if (i < N4H)            { src = Wh; dst = g_Wh; idx = i; }
        else if (i < N4H + N4O) { src = Wo; dst = g_Wo; idx = i - N4H; }
        else continue;
        const float4 v = __ldcs(src + idx);
        const __half2 h0 = __floats2half2_rn(v.x, v.y);
        const __half2 h1 = __floats2half2_rn(v.z, v.w);
        uint2 u;
        u.x = *reinterpret_cast<const uint32_t*>(&h0);
        u.y = *reinterpret_cast<const uint32_t*>(&h1);
        *reinterpret_cast<uint2*>(dst + (size_t)idx * 4) = u;
    }
}

// ---------------- launcher ----------------
extern "C" void kernel_launch(void* const* d_in, const int* in_sizes, int n_in,
                              void* d_out, int out_size) {
    const float* psp   = (const float*)d_in[0];  // [1024, 4096]
    const float* label = (const float*)d_in[1];  // [4096, 512]
    const float* W_h   = (const float*)d_in[2];  // [2048, 1024]
    const float* b_h   = (const float*)d_in[3];  // [2048]
    const float* W_o   = (const float*)d_in[4];  // [512, 2048]
    const float* b_o   = (const float*)d_in[5];  // [512]
    float* out = (float*)d_out;                  // [4096, 512]

    const int SMEM = 3 * 32768 + 64;
    cudaFuncSetAttribute(k_gemm<IN_SZ, 0>,  cudaFuncAttributeMaxDynamicSharedMemorySize, SMEM);
    cudaFuncSetAttribute(k_gemm<HID_SZ, 2>, cudaFuncAttributeMaxDynamicSharedMemorySize, SMEM);

    const int PREP_BLOCKS = (B_SZ / 128) * (IN_SZ / 32)
                          + (HID_SZ * IN_SZ / 4 + OUT_SZ * HID_SZ / 4 + 1023) / 1024;
    k_prep<<<PREP_BLOCKS, 256>>>(psp, (const float4*)W_h, (const float4*)W_o);

    k_gemm<IN_SZ, 0><<<dim3(B_SZ / 128, HID_SZ / 128), 256, SMEM>>>(b_h);
    k_gemm<HID_SZ, 2><<<dim3(B_SZ / 128, OUT_SZ / 128, 2), 256, SMEM>>>(nullptr);
    k_red<<<B_SZ * OUT_SZ / 4 / 256, 256>>>(b_o, label, out);
}